// round 1
// baseline (speedup 1.0000x reference)
#include <cuda_runtime.h>
#include <cuda_bf16.h>
#include <mma.h>

using namespace nvcuda;

#define N_ROWS 4096
#define DIM    512
#define BM 128
#define BN 128
#define BK 32
#define LDS 144   // smem leading dim in elements (multiple of 8, 16B-aligned rows)

// Scratch: normalized bf16 copies of the 4 inputs (order: rgb, depth, ir, t)
static __device__ __nv_bfloat16 g_norm[4][N_ROWS][DIM];
// Per-tile weighted sum-of-squares partials: 7 products x 16 tiles
static __device__ float g_part[112];

// Product table: left matrix, right matrix, weight
//   indices into g_norm: 0=rgb, 1=depth, 2=ir, 3=t
__constant__ int   c_L[7] = {3, 0, 1, 2, 3, 3, 3};
__constant__ int   c_R[7] = {3, 0, 1, 2, 0, 1, 2};
__constant__ float c_W[7] = {3.f, 1.f, 1.f, 1.f, -2.f, -2.f, -2.f};

// ---------------------------------------------------------------------------
// K1: row-wise L2 normalize, fp32 -> bf16 scratch. One block per row.
// ---------------------------------------------------------------------------
__global__ __launch_bounds__(128) void normalize_kernel(
    const float* __restrict__ in0, const float* __restrict__ in1,
    const float* __restrict__ in2, const float* __restrict__ in3)
{
    int row = blockIdx.x;        // 0 .. 16383
    int mat = row >> 12;         // which matrix
    int r   = row & (N_ROWS - 1);
    const float* src = (mat == 0) ? in0 : (mat == 1) ? in1 : (mat == 2) ? in2 : in3;
    src += (size_t)r * DIM;

    int t = threadIdx.x;         // 128 threads, 4 elements each
    float v[4];
    float ss = 0.f;
#pragma unroll
    for (int j = 0; j < 4; j++) {
        v[j] = src[t + j * 128];
        ss += v[j] * v[j];
    }
    // block reduce (4 warps)
    __shared__ float red[4];
#pragma unroll
    for (int o = 16; o > 0; o >>= 1) ss += __shfl_xor_sync(0xffffffffu, ss, o);
    if ((t & 31) == 0) red[t >> 5] = ss;
    __syncthreads();
    float tot = red[0] + red[1] + red[2] + red[3];
    // matches 1/max(sqrt(ss), 1e-12)
    float inv = rsqrtf(fmaxf(tot, 1e-24f));

    __nv_bfloat16* dst = &g_norm[mat][r][0];
#pragma unroll
    for (int j = 0; j < 4; j++)
        dst[t + j * 128] = __float2bfloat16(v[j] * inv);
}

// ---------------------------------------------------------------------------
// K2: one 128x128 output tile of C = P^T Q (D x D, K = 4096), bf16 HMMA,
//     fp32 accumulate, fused sum-of-squares epilogue.
// grid = (4, 4, 7): x = n-tile, y = m-tile, z = product index.
// ---------------------------------------------------------------------------
__global__ __launch_bounds__(256) void gram_tile_kernel()
{
    const int p  = blockIdx.z;
    const __nv_bfloat16* __restrict__ A = &g_norm[c_L[p]][0][0];  // [K, DIM]
    const __nv_bfloat16* __restrict__ B = &g_norm[c_R[p]][0][0];  // [K, DIM]
    const int m0 = blockIdx.y * BM;
    const int n0 = blockIdx.x * BN;

    __shared__ __nv_bfloat16 As[BK][LDS];   // [k][m]  (col-major for matrix_a)
    __shared__ __nv_bfloat16 Bs[BK][LDS];   // [k][n]  (row-major for matrix_b)

    const int tid = threadIdx.x;
    const int wid = tid >> 5;               // 8 warps: 2 (M) x 4 (N)
    const int warp_m = (wid & 1) * 64;      // 64 rows per warp
    const int warp_n = (wid >> 1) * 32;     // 32 cols per warp

    wmma::fragment<wmma::accumulator, 16, 16, 16, float> acc[4][2];
#pragma unroll
    for (int i = 0; i < 4; i++)
#pragma unroll
        for (int j = 0; j < 2; j++) wmma::fill_fragment(acc[i][j], 0.f);

    for (int k0 = 0; k0 < N_ROWS; k0 += BK) {
        // Cooperative tile load: 32 rows x 128 bf16 = 512 uint4 per tile.
#pragma unroll
        for (int l = 0; l < 2; l++) {
            int idx = tid + l * 256;               // 0..511
            int kk  = idx >> 4;                    // row within k-tile
            int q   = idx & 15;                    // uint4 within row
            const uint4* ga = (const uint4*)(A + (size_t)(k0 + kk) * DIM + m0) + q;
            const uint4* gb = (const uint4*)(B + (size_t)(k0 + kk) * DIM + n0) + q;
            *(uint4*)(&As[kk][q * 8]) = *ga;
            *(uint4*)(&Bs[kk][q * 8]) = *gb;
        }
        __syncthreads();

#pragma unroll
        for (int ks = 0; ks < BK; ks += 16) {
            wmma::fragment<wmma::matrix_a, 16, 16, 16, __nv_bfloat16, wmma::col_major> af[4];
            wmma::fragment<wmma::matrix_b, 16, 16, 16, __nv_bfloat16, wmma::row_major> bf[2];
#pragma unroll
            for (int i = 0; i < 4; i++)
                wmma::load_matrix_sync(af[i], &As[ks][warp_m + i * 16], LDS);
#pragma unroll
            for (int j = 0; j < 2; j++)
                wmma::load_matrix_sync(bf[j], &Bs[ks][warp_n + j * 16], LDS);
#pragma unroll
            for (int i = 0; i < 4; i++)
#pragma unroll
                for (int j = 0; j < 2; j++)
                    wmma::mma_sync(acc[i][j], af[i], bf[j], acc[i][j]);
        }
        __syncthreads();
    }

    // Fused epilogue: weighted sum of squares of this tile.
    float ss = 0.f;
#pragma unroll
    for (int i = 0; i < 4; i++)
#pragma unroll
        for (int j = 0; j < 2; j++)
#pragma unroll
            for (int e = 0; e < acc[i][j].num_elements; e++) {
                float x = acc[i][j].x[e];
                ss += x * x;
            }
#pragma unroll
    for (int o = 16; o > 0; o >>= 1) ss += __shfl_xor_sync(0xffffffffu, ss, o);
    __shared__ float red[8];
    if ((tid & 31) == 0) red[wid] = ss;
    __syncthreads();
    if (tid == 0) {
        float tot = 0.f;
#pragma unroll
        for (int w = 0; w < 8; w++) tot += red[w];
        g_part[p * 16 + blockIdx.y * 4 + blockIdx.x] = c_W[p] * tot;
    }
}

// ---------------------------------------------------------------------------
// K3: deterministic fixed-order reduction of 112 partials -> scalar loss.
// loss = (100 / N^2) * sum_p w_p * ||C_p||_F^2
// ---------------------------------------------------------------------------
__global__ __launch_bounds__(128) void reduce_kernel(float* __restrict__ out)
{
    __shared__ float s[128];
    int t = threadIdx.x;
    s[t] = (t < 112) ? g_part[t] : 0.f;
    __syncthreads();
#pragma unroll
    for (int o = 64; o > 0; o >>= 1) {
        if (t < o) s[t] += s[t + o];
        __syncthreads();
    }
    if (t == 0) out[0] = s[0] * (100.0f / 16777216.0f);   // 100 / 4096^2
}

// ---------------------------------------------------------------------------
extern "C" void kernel_launch(void* const* d_in, const int* in_sizes, int n_in,
                              void* d_out, int out_size)
{
    const float* rgb   = (const float*)d_in[0];
    const float* depth = (const float*)d_in[1];
    const float* ir    = (const float*)d_in[2];
    const float* tmat  = (const float*)d_in[3];
    float* out = (float*)d_out;

    normalize_kernel<<<4 * N_ROWS, 128>>>(rgb, depth, ir, tmat);

    dim3 grid(4, 4, 7);
    gram_tile_kernel<<<grid, 256>>>();

    reduce_kernel<<<1, 128>>>(out);
}

// round 4
// speedup vs baseline: 2.3055x; 2.3055x over previous
#include <cuda_runtime.h>
#include <cuda_bf16.h>
#include <cstdint>

#define N_ROWS 4096
#define DIM    512
#define BM 128
#define BN 128
#define BK 64
#define K_ITERS (N_ROWS / BK)            // 64
#define TILE_BYTES (128 * 128)           // 128 rows x 128B (BK=64 bf16)
#define STAGE_BYTES (2 * TILE_BYTES)     // A + B
#define STAGES 3
#define SMEM_DYN (STAGES * STAGE_BYTES + 1024)

// Scratch: transposed normalized bf16: [mat][d][k], k contiguous
static __device__ __nv_bfloat16 g_normT[4][DIM][N_ROWS];
static __device__ float g_inv[4 * N_ROWS];
static __device__ float g_part[112];

__constant__ int   c_L[7] = {3, 0, 1, 2, 3, 3, 3};
__constant__ int   c_R[7] = {3, 0, 1, 2, 0, 1, 2};
__constant__ float c_W[7] = {3.f, 1.f, 1.f, 1.f, -2.f, -2.f, -2.f};

// ---------------------------------------------------------------------------
__device__ __forceinline__ uint32_t s2u(const void* p) {
    uint32_t a;
    asm("{ .reg .u64 t; cvta.to.shared.u64 t, %1; cvt.u32.u64 %0, t; }"
        : "=r"(a) : "l"(p));
    return a;
}
__device__ __forceinline__ void cpasync16(uint32_t dst, const void* src) {
    asm volatile("cp.async.cg.shared.global [%0], [%1], 16;" :: "r"(dst), "l"(src) : "memory");
}
__device__ __forceinline__ void ldsm4(uint32_t& r0, uint32_t& r1, uint32_t& r2,
                                      uint32_t& r3, uint32_t addr) {
    asm volatile("ldmatrix.sync.aligned.m8n8.x4.shared.b16 {%0,%1,%2,%3}, [%4];"
                 : "=r"(r0), "=r"(r1), "=r"(r2), "=r"(r3) : "r"(addr));
}
__device__ __forceinline__ void mma16816(float* c, const uint32_t* a, const uint32_t* b) {
    asm volatile(
        "mma.sync.aligned.m16n8k16.row.col.f32.bf16.bf16.f32 "
        "{%0,%1,%2,%3}, {%4,%5,%6,%7}, {%8,%9}, {%0,%1,%2,%3};"
        : "+f"(c[0]), "+f"(c[1]), "+f"(c[2]), "+f"(c[3])
        : "r"(a[0]), "r"(a[1]), "r"(a[2]), "r"(a[3]), "r"(b[0]), "r"(b[1]));
}

// ---------------------------------------------------------------------------
// K1a: per-row inverse L2 norm. One warp per row.
// ---------------------------------------------------------------------------
__global__ __launch_bounds__(256) void norm_kernel(
    const float* __restrict__ in0, const float* __restrict__ in1,
    const float* __restrict__ in2, const float* __restrict__ in3)
{
    int row  = blockIdx.x * 8 + (threadIdx.x >> 5);   // 0..16383
    int lane = threadIdx.x & 31;
    int mat  = row >> 12;
    int r    = row & (N_ROWS - 1);
    const float* src = (mat == 0) ? in0 : (mat == 1) ? in1 : (mat == 2) ? in2 : in3;
    src += (size_t)r * DIM + lane;
    float ss = 0.f;
#pragma unroll
    for (int i = 0; i < 16; i++) { float v = src[i * 32]; ss += v * v; }
#pragma unroll
    for (int o = 16; o > 0; o >>= 1) ss += __shfl_xor_sync(0xffffffffu, ss, o);
    if (lane == 0) g_inv[row] = rsqrtf(fmaxf(ss, 1e-24f));   // 1/max(||x||,1e-12)
}

// ---------------------------------------------------------------------------
// K1b: normalize + transpose fp32[k][d] -> bf16 g_normT[d][k]. 64x64 tiles.
// ---------------------------------------------------------------------------
__global__ __launch_bounds__(256) void transpose_kernel(
    const float* __restrict__ in0, const float* __restrict__ in1,
    const float* __restrict__ in2, const float* __restrict__ in3)
{
    __shared__ float tile[64][65];
    const int mat = blockIdx.z;
    const int k0 = blockIdx.x * 64;
    const int d0 = blockIdx.y * 64;
    const float* src = (mat == 0) ? in0 : (mat == 1) ? in1 : (mat == 2) ? in2 : in3;
    const int t = threadIdx.x;

#pragma unroll
    for (int i = 0; i < 16; i++) {
        int idx = t + i * 256;
        int r = idx >> 6, c = idx & 63;            // r: k-local, c: d-local
        tile[r][c] = src[(size_t)(k0 + r) * DIM + d0 + c] * g_inv[mat * N_ROWS + k0 + r];
    }
    __syncthreads();
#pragma unroll
    for (int i = 0; i < 8; i++) {
        int idx = t + i * 256;
        int r = idx >> 5;                          // d-local 0..63
        int c2 = (idx & 31) * 2;                   // k-local pair
        __nv_bfloat162 h2;
        h2.x = __float2bfloat16(tile[c2][r]);
        h2.y = __float2bfloat16(tile[c2 + 1][r]);
        *reinterpret_cast<__nv_bfloat162*>(&g_normT[mat][d0 + r][k0 + c2]) = h2;
    }
}

// ---------------------------------------------------------------------------
// K2: pipelined mma.sync bf16 GEMM tile C[128,128] = A * B^T (K=4096),
//     fused ||C||_F^2 epilogue. grid (4,4,7), 256 threads (8 warps, 2x4).
// smem: 3 stages x (A tile + B tile), rows 128B, 16B chunk c swizzled c^(row&7)
// ---------------------------------------------------------------------------
__global__ __launch_bounds__(256, 1) void gram_kernel()
{
    extern __shared__ char dyn[];
    __shared__ float red[8];

    const int p  = blockIdx.z;
    const int m0 = blockIdx.y * BM;
    const int n0 = blockIdx.x * BN;
    const char* __restrict__ Ab = (const char*)&g_normT[c_L[p]][0][0];
    const char* __restrict__ Bb = (const char*)&g_normT[c_R[p]][0][0];

    const int tid  = threadIdx.x;
    const int lane = tid & 31;
    const int wid  = tid >> 5;
    const int warp_m = (wid & 1) * 64;       // 2 warps along M
    const int warp_n = (wid >> 1) * 32;      // 4 warps along N
    const uint32_t dynb = (s2u(dyn) + 1023) & ~1023u;

    // ---- per-thread cp.async slots: 2048 16B chunks (A then B), 8/thread
    auto issue_loads = [&](int it) {
        uint32_t sbase = dynb + (uint32_t)(it % STAGES) * STAGE_BYTES;
#pragma unroll
        for (int q = 0; q < 8; q++) {
            int c   = tid + q * 256;
            int isB = c >> 10;
            int row = (c & 1023) >> 3;
            int q16 = c & 7;
            uint32_t sw = (uint32_t)row * 128 + (uint32_t)((q16 ^ (row & 7)) << 4);
            const char* g = (isB ? Bb : Ab)
                          + ((size_t)((isB ? n0 : m0) + row) << 13)   // row * 8192B
                          + (size_t)it * 128 + q16 * 16;
            cpasync16(sbase + (isB ? TILE_BYTES : 0) + sw, g);
        }
        asm volatile("cp.async.commit_group;" ::: "memory");
    };

    // ---- precompute ldmatrix row addressing
    // A frags (m16): lanes 0-15 -> rows, lane>>4 -> k 16B half
    uint32_t a_off[4], a_xor[4];
#pragma unroll
    for (int i = 0; i < 4; i++) {
        int row = warp_m + i * 16 + (lane & 15);
        a_off[i] = (uint32_t)row * 128;
        a_xor[i] = (uint32_t)(row & 7);
    }
    const uint32_t a_hi = (uint32_t)(lane >> 4);          // 0/1
    // B frags (n16 per ldsm.x4): rows n, chunks per lane group
    uint32_t b_off[2], b_xor[2];
#pragma unroll
    for (int g = 0; g < 2; g++) {
        int row = warp_n + g * 16 + ((lane >> 4) & 1) * 8 + (lane & 7);
        b_off[g] = (uint32_t)row * 128;
        b_xor[g] = (uint32_t)(row & 7);
    }
    const uint32_t b_hi = (uint32_t)((lane >> 3) & 1);    // 0/1

    float acc[4][4][4];
#pragma unroll
    for (int i = 0; i < 4; i++)
#pragma unroll
        for (int j = 0; j < 4; j++)
#pragma unroll
            for (int r = 0; r < 4; r++) acc[i][j][r] = 0.f;

    issue_loads(0);
    issue_loads(1);

    for (int it = 0; it < K_ITERS; ++it) {
        if (it < K_ITERS - 1)
            asm volatile("cp.async.wait_group 1;" ::: "memory");
        else
            asm volatile("cp.async.wait_group 0;" ::: "memory");
        __syncthreads();

        const uint32_t sA = dynb + (uint32_t)(it % STAGES) * STAGE_BYTES;
        const uint32_t sB = sA + TILE_BYTES;

#pragma unroll
        for (int kk = 0; kk < 4; kk++) {                  // 4 x k16 per BK=64
            const uint32_t ca = (uint32_t)(kk * 2) + a_hi;
            const uint32_t cb = (uint32_t)(kk * 2) + b_hi;
            uint32_t a[4][4];
#pragma unroll
            for (int i = 0; i < 4; i++)
                ldsm4(a[i][0], a[i][1], a[i][2], a[i][3],
                      sA + a_off[i] + ((ca ^ a_xor[i]) << 4));
            uint32_t bf[4][2];
#pragma unroll
            for (int g = 0; g < 2; g++) {
                uint32_t r0, r1, r2, r3;
                ldsm4(r0, r1, r2, r3, sB + b_off[g] + ((cb ^ b_xor[g]) << 4));
                bf[g * 2 + 0][0] = r0; bf[g * 2 + 0][1] = r1;   // n8 lo
                bf[g * 2 + 1][0] = r2; bf[g * 2 + 1][1] = r3;   // n8 hi
            }
#pragma unroll
            for (int i = 0; i < 4; i++)
#pragma unroll
                for (int j = 0; j < 4; j++)
                    mma16816(acc[i][j], a[i], bf[j]);
        }

        const int nx = it + 2;
        if (nx < K_ITERS) issue_loads(nx);
    }

    // ---- fused epilogue: weighted sum of squares
    float ss = 0.f;
#pragma unroll
    for (int i = 0; i < 4; i++)
#pragma unroll
        for (int j = 0; j < 4; j++)
#pragma unroll
            for (int r = 0; r < 4; r++) {
                float x = acc[i][j][r];
                ss += x * x;
            }
#pragma unroll
    for (int o = 16; o > 0; o >>= 1) ss += __shfl_xor_sync(0xffffffffu, ss, o);
    if (lane == 0) red[wid] = ss;
    __syncthreads();
    if (tid == 0) {
        float tot = 0.f;
#pragma unroll
        for (int w = 0; w < 8; w++) tot += red[w];
        g_part[p * 16 + blockIdx.y * 4 + blockIdx.x] = c_W[p] * tot;
    }
}

// ---------------------------------------------------------------------------
// K3: deterministic fixed-order reduction of 112 partials -> scalar loss.
// ---------------------------------------------------------------------------
__global__ __launch_bounds__(128) void reduce_kernel(float* __restrict__ out)
{
    __shared__ float s[128];
    int t = threadIdx.x;
    s[t] = (t < 112) ? g_part[t] : 0.f;
    __syncthreads();
#pragma unroll
    for (int o = 64; o > 0; o >>= 1) {
        if (t < o) s[t] += s[t + o];
        __syncthreads();
    }
    if (t == 0) out[0] = s[0] * (100.0f / 16777216.0f);   // (1/T^2) / N^2
}

// ---------------------------------------------------------------------------
extern "C" void kernel_launch(void* const* d_in, const int* in_sizes, int n_in,
                              void* d_out, int out_size)
{
    const float* rgb   = (const float*)d_in[0];
    const float* depth = (const float*)d_in[1];
    const float* ir    = (const float*)d_in[2];
    const float* tmat  = (const float*)d_in[3];
    float* out = (float*)d_out;

    cudaFuncSetAttribute(gram_kernel, cudaFuncAttributeMaxDynamicSharedMemorySize, SMEM_DYN);

    norm_kernel<<<2048, 256>>>(rgb, depth, ir, tmat);

    dim3 tgrid(N_ROWS / 64, DIM / 64, 4);
    transpose_kernel<<<tgrid, 256>>>(rgb, depth, ir, tmat);

    dim3 ggrid(4, 4, 7);
    gram_kernel<<<ggrid, 256, SMEM_DYN>>>();

    reduce_kernel<<<1, 128>>>(out);
}